// round 13
// baseline (speedup 1.0000x reference)
#include <cuda_runtime.h>
#include <cuda_fp16.h>
#include <math.h>

// ---------------------------------------------------------------------------
// Shapes
// ---------------------------------------------------------------------------
#define BB 32
#define LL 128
#define NN 512
#define JJ 21
#define HAND_DIM 99
#define DD 512
#define HH 8
#define DHH 64
#define DFF 2048
#define CAT 1249
#define CATP 1280
#define SS 256
#define ROWS 4096
#define TROWS 8192

#define F_X 0
#define F_J 99
#define F_MC 162
#define F_PCN 674
#define F_ATT 1186

// ---------------------------------------------------------------------------
// Scratch: fp32 kept only where consumed by non-GEMM ops
// ---------------------------------------------------------------------------
__device__ float g_x   [TROWS * DD];
__device__ float g_q   [TROWS * DD];
__device__ float g_proj[TROWS * DD];
__device__ float g_x1  [TROWS * DD];
__device__ float g_f   [TROWS * DD];

// fp16 activation buffers (GEMM A inputs)
__device__ __align__(16) __half g_feat16_l[ROWS * CATP];
__device__ __align__(16) __half g_feat16_r[ROWS * CATP];
__device__ __align__(16) __half g_x16  [TROWS * DD];
__device__ __align__(16) __half g_k16  [TROWS * DD];
__device__ __align__(16) __half g_v16  [TROWS * DD];
__device__ __align__(16) __half g_ao16 [TROWS * DD];
__device__ __align__(16) __half g_x116 [TROWS * DD];
__device__ __align__(16) __half g_h16  [TROWS * DFF];
__device__ __align__(16) __half g_x216 [TROWS * DD];

// fp16 weights
__device__ __align__(16) __half g_wfc_l16[CAT * DD];
__device__ __align__(16) __half g_wfc_r16[CAT * DD];
__device__ __align__(16) __half g_wq16 [DD * DD];
__device__ __align__(16) __half g_wk16 [DD * DD];
__device__ __align__(16) __half g_wv16 [DD * DD];
__device__ __align__(16) __half g_wo16 [DD * DD];
__device__ __align__(16) __half g_w116 [DD * DFF];
__device__ __align__(16) __half g_w216 [DFF * DD];
__device__ __align__(16) __half g_woutl16[DD * 128];
__device__ __align__(16) __half g_woutr16[DD * 128];

// ---------------------------------------------------------------------------
// Weight conversion
// ---------------------------------------------------------------------------
struct CvtJobs {
    const float* src[8];
    __half* dst[8];
    int n4[8];
};
__global__ void cvt_weights_kernel(CvtJobs cj)
{
    int gid = blockIdx.x * blockDim.x + threadIdx.x;
    int stride = gridDim.x * blockDim.x;
    #pragma unroll
    for (int j = 0; j < 8; j++) {
        const float4* s = (const float4*)cj.src[j];
        __half2* d = (__half2*)cj.dst[j];
        int n4 = cj.n4[j];
        for (int i = gid; i < n4; i += stride) {
            float4 v = s[i];
            d[2*i]   = __floats2half2_rn(v.x, v.y);
            d[2*i+1] = __floats2half2_rn(v.z, v.w);
        }
    }
}

__global__ void pad_wout_kernel(const float* __restrict__ Wl, const float* __restrict__ Wr,
                                __half* __restrict__ dl, __half* __restrict__ dr)
{
    int idx = blockIdx.x * 256 + threadIdx.x;
    int row = idx >> 7, col = idx & 127;
    float vl = (col < HAND_DIM) ? Wl[row*HAND_DIM + col] : 0.f;
    float vr = (col < HAND_DIM) ? Wr[row*HAND_DIM + col] : 0.f;
    dl[idx] = __float2half_rn(vl);
    dr[idx] = __float2half_rn(vr);
}

// ---------------------------------------------------------------------------
// Feature build -> fp16 feature rows
// ---------------------------------------------------------------------------
__global__ void build_features_kernel(
    const float* __restrict__ x_l, const float* __restrict__ x_r,
    const float* __restrict__ j_l, const float* __restrict__ j_r,
    const float* __restrict__ m_contact, const float* __restrict__ pc,
    __half* __restrict__ feat_l, __half* __restrict__ feat_r)
{
    int m = blockIdx.x;
    int b = m >> 7;
    __shared__ float px[NN], py[NN], pz[NN];
    int tid = threadIdx.x;

    const float* pcb = pc + (size_t)m * NN * 3;
    for (int n = tid; n < NN; n += 256) {
        px[n] = pcb[n*3+0]; py[n] = pcb[n*3+1]; pz[n] = pcb[n*3+2];
    }
    __syncthreads();

    __half* fl = feat_l + (size_t)m * CATP;
    __half* fr = feat_r + (size_t)m * CATP;

    for (int i = tid; i < HAND_DIM; i += 256) {
        fl[F_X+i] = __float2half_rn(x_l[(size_t)m*HAND_DIM + i]);
        fr[F_X+i] = __float2half_rn(x_r[(size_t)m*HAND_DIM + i]);
    }
    for (int i = tid; i < JJ*3; i += 256) {
        fl[F_J+i] = __float2half_rn(j_l[(size_t)m*JJ*3 + i]);
        fr[F_J+i] = __float2half_rn(j_r[(size_t)m*JJ*3 + i]);
    }
    for (int n = tid; n < NN; n += 256) {
        __half mc = __float2half_rn(m_contact[b*NN + n]);
        fl[F_MC+n] = mc; fr[F_MC+n] = mc;
        __half nm = __float2half_rn(sqrtf(px[n]*px[n] + py[n]*py[n] + pz[n]*pz[n]));
        fl[F_PCN+n] = nm; fr[F_PCN+n] = nm;
    }
    __half z = __float2half_rn(0.f);
    for (int i = CAT + tid; i < CATP; i += 256) { fl[i] = z; fr[i] = z; }

    int w = tid >> 5, lane = tid & 31;
    for (int task = w; task < 2*JJ; task += 8) {
        int hand = task / JJ, joint = task % JJ;
        const float* jb = (hand == 0 ? j_l : j_r) + ((size_t)m*JJ + joint)*3;
        float jx = jb[0], jy = jb[1], jz = jb[2];
        float best = 3.402823466e+38f; int bi = 0;
        for (int n = lane; n < NN; n += 32) {
            float dx = jx - px[n], dy = jy - py[n], dz = jz - pz[n];
            float d2 = dx*dx + dy*dy + dz*dz;
            if (d2 < best) { best = d2; bi = n; }
        }
        for (int off = 16; off; off >>= 1) {
            float ob = __shfl_xor_sync(0xffffffffu, best, off);
            int   oi = __shfl_xor_sync(0xffffffffu, bi, off);
            if (ob < best || (ob == best && oi < bi)) { best = ob; bi = oi; }
        }
        if (lane == 0) {
            float dx = jx - px[bi], dy = jy - py[bi], dz = jz - pz[bi];
            __half* f = (hand == 0 ? fl : fr);
            f[F_ATT + joint*3 + 0] = __float2half_rn(expf(-50.f * dx * dx));
            f[F_ATT + joint*3 + 1] = __float2half_rn(expf(-50.f * dy * dy));
            f[F_ATT + joint*3 + 2] = __float2half_rn(expf(-50.f * dz * dz));
        }
    }
}

// ---------------------------------------------------------------------------
// Epilogues
// ---------------------------------------------------------------------------
struct EpiParams {
    const float* bias;
    const float* mask;
    const unsigned char* pad;
    int hand;
    int relu;
    int nreal;
};

#define LN10000 9.2103403719761827f

template<int EPI>
__device__ __forceinline__ float apply_epi(float v, int row, int col, const EpiParams& ep)
{
    if (EPI == 0) {
        if (ep.bias) v += ep.bias[col];
        if (ep.relu) v = fmaxf(v, 0.f);
    } else if (EPI == 1) {
        int l = row & 127;
        int ii = col >> 1;
        float freq = expf(-LN10000 * (float)ii * (1.f/256.f));
        float angF = (float)l * freq;
        float angA = (float)ep.hand * freq;
        float pe = (col & 1) ? (cosf(angF) + cosf(angA))
                             : (sinf(angF) + sinf(angA));
        float mv = ep.mask[row] * (ep.pad[2*row + ep.hand] ? 0.f : 1.f);
        v = (v + ep.bias[col] + pe) * mv;
    } else { // EPI == 2
        float mv = ep.mask[row] * (ep.pad[2*row + ep.hand] ? 0.f : 1.f);
        v = (v + ep.bias[col]) * mv;
    }
    return v;
}

// ---------------------------------------------------------------------------
// Multi-job single-pass fp16 GEMM, 3-stage cp.async ring, 1 barrier/k-tile.
// 128 threads, tile 64x64, BK=32, 4 warps (2x2, warp tile 32x32), 6 CTAs/SM.
// ---------------------------------------------------------------------------
struct Job { const __half* A; const __half* B; float* C; __half* C16; EpiParams ep; };
template<int NJ> struct Jobs { Job j[NJ]; };

#define PA 80
#define PB 144
#define A_BYTES (64*PA)                // 5120
#define B_BYTES (32*PB)                // 4608
#define OFF_AH 0
#define OFF_BH (A_BYTES)
#define BUF_BYTES (A_BYTES + B_BYTES)     // 9728
#define STAGES 3
#define TG_SMEM (STAGES*BUF_BYTES)        // 29184

__device__ __forceinline__ unsigned smem_u32(const void* p) {
    return (unsigned)__cvta_generic_to_shared(p);
}
__device__ __forceinline__ void ldsm4(unsigned* r, unsigned addr) {
    asm volatile("ldmatrix.sync.aligned.m8n8.x4.shared.b16 {%0,%1,%2,%3}, [%4];"
        : "=r"(r[0]), "=r"(r[1]), "=r"(r[2]), "=r"(r[3]) : "r"(addr));
}
__device__ __forceinline__ void ldsm4t(unsigned* r, unsigned addr) {
    asm volatile("ldmatrix.sync.aligned.m8n8.x4.trans.shared.b16 {%0,%1,%2,%3}, [%4];"
        : "=r"(r[0]), "=r"(r[1]), "=r"(r[2]), "=r"(r[3]) : "r"(addr));
}
__device__ __forceinline__ void mma16816(float* c, const unsigned* a, unsigned b0, unsigned b1) {
    asm volatile(
        "mma.sync.aligned.m16n8k16.row.col.f32.f16.f16.f32 "
        "{%0,%1,%2,%3}, {%4,%5,%6,%7}, {%8,%9}, {%0,%1,%2,%3};"
        : "+f"(c[0]), "+f"(c[1]), "+f"(c[2]), "+f"(c[3])
        : "r"(a[0]), "r"(a[1]), "r"(a[2]), "r"(a[3]), "r"(b0), "r"(b1));
}
__device__ __forceinline__ void cp16(unsigned dst, const void* src, bool full) {
    int sz = full ? 16 : 0;
    asm volatile("cp.async.cg.shared.global [%0], [%1], 16, %2;"
                 :: "r"(dst), "l"(src), "r"(sz) : "memory");
}
__device__ __forceinline__ void cp_commit() {
    asm volatile("cp.async.commit_group;" ::: "memory");
}
template<int N> __device__ __forceinline__ void cp_wait() {
    asm volatile("cp.async.wait_group %0;" :: "n"(N) : "memory");
}

template<int EPI, int GUARD, int NJ>
__global__ __launch_bounds__(128, 6)
void tgemm(Jobs<NJ> jobs, int lda, int ldb, int ldc, int M, int N, int Kreal)
{
    const Job& jb = jobs.j[blockIdx.z];
    const __half* __restrict__ A = jb.A;
    const __half* __restrict__ B = jb.B;
    float* __restrict__ C = jb.C;
    __half* __restrict__ C16 = jb.C16;
    EpiParams ep = jb.ep;

    extern __shared__ unsigned char smraw[];
    unsigned sbase = smem_u32(smraw);
    int tid = threadIdx.x, lane = tid & 31, wid = tid >> 5;
    int warp_m = wid & 1, warp_n = wid >> 1;
    int m0 = blockIdx.y * 64, n0 = blockIdx.x * 64;
    int g = lane >> 2, t = lane & 3;

    float acc[2][4][4];
    #pragma unroll
    for (int i = 0; i < 2; i++)
        #pragma unroll
        for (int j = 0; j < 4; j++)
            #pragma unroll
            for (int e = 0; e < 4; e++) acc[i][j][e] = 0.f;

    int aRow = lane & 15;
    int aKof = ((lane >> 4) & 1) * 8;
    int bRow = lane & 15;
    int bNof = ((lane >> 4) & 1) * 8;

    int nk = (Kreal + 31) >> 5;

    auto prefetch = [&](int kt) {
        int k0 = kt * 32;
        unsigned bufb = sbase + (kt % STAGES) * BUF_BYTES;
        #pragma unroll
        for (int i = 0; i < 2; i++) {
            int c = tid + 128*i;
            int r = c >> 2, col8 = (c & 3) * 8;
            cp16(bufb + OFF_AH + r*PA + col8*2,
                 A + (size_t)(m0 + r)*lda + k0 + col8, true);
        }
        #pragma unroll
        for (int i = 0; i < 2; i++) {
            int c = tid + 128*i;
            int r = c >> 3, col8 = (c & 7) * 8;
            int k = k0 + r;
            int ksafe = (k < Kreal) ? k : (Kreal - 1);
            cp16(bufb + OFF_BH + r*PB + col8*2,
                 B + (size_t)ksafe*ldb + n0 + col8, k < Kreal);
        }
        cp_commit();
    };

    // nk >= 2 always holds here (min K = 512)
    prefetch(0);
    prefetch(1);

    for (int kt = 0; kt < nk; kt++) {
        cp_wait<1>();               // group kt complete (tail kept aligned below)
        __syncthreads();            // visibility + WAR for buffer (kt-1)%3
        if (kt + 2 < nk) prefetch(kt + 2);
        else             cp_commit();   // empty group keeps FIFO accounting

        unsigned base = sbase + (kt % STAGES) * BUF_BYTES;
        #pragma unroll
        for (int ks = 0; ks < 2; ks++) {
            unsigned aAddrBase = base + (ks*16 + aKof) * 2;
            unsigned bAddrBase = base + (ks*16 + bRow) * PB;

            unsigned ah[2][4], bh[2][4];
            #pragma unroll
            for (int mt = 0; mt < 2; mt++)
                ldsm4(ah[mt], aAddrBase + OFF_AH + (warp_m*32 + mt*16 + aRow)*PA);
            #pragma unroll
            for (int np = 0; np < 2; np++)
                ldsm4t(bh[np], bAddrBase + OFF_BH + (warp_n*32 + np*16 + bNof)*2);

            #pragma unroll
            for (int mt = 0; mt < 2; mt++)
                #pragma unroll
                for (int nt = 0; nt < 4; nt++)
                    mma16816(acc[mt][nt], ah[mt], bh[nt>>1][(nt&1)*2], bh[nt>>1][(nt&1)*2+1]);
        }
    }

    #pragma unroll
    for (int mt = 0; mt < 2; mt++) {
        int row0 = m0 + warp_m*32 + mt*16 + g;
        #pragma unroll
        for (int nt = 0; nt < 4; nt++) {
            int col = n0 + warp_n*32 + nt*8 + t*2;
            float* c = acc[mt][nt];
            float v0 = apply_epi<EPI>(c[0], row0,     col,     ep);
            float v1 = apply_epi<EPI>(c[1], row0,     col + 1, ep);
            float v2 = apply_epi<EPI>(c[2], row0 + 8, col,     ep);
            float v3 = apply_epi<EPI>(c[3], row0 + 8, col + 1, ep);
            if (GUARD) {
                if (C) {
                    if (col < ep.nreal)     C[(size_t)row0*ldc + col]         = v0;
                    if (col + 1 < ep.nreal) C[(size_t)row0*ldc + col + 1]     = v1;
                    if (col < ep.nreal)     C[(size_t)(row0+8)*ldc + col]     = v2;
                    if (col + 1 < ep.nreal) C[(size_t)(row0+8)*ldc + col + 1] = v3;
                }
            } else {
                if (C) {
                    *(float2*)(C + (size_t)row0*ldc + col)       = make_float2(v0, v1);
                    *(float2*)(C + (size_t)(row0 + 8)*ldc + col) = make_float2(v2, v3);
                }
                if (C16) {
                    __half2 h01 = __floats2half2_rn(v0, v1);
                    __half2 h23 = __floats2half2_rn(v2, v3);
                    *(__half2*)(C16 + (size_t)row0*ldc + col)       = h01;
                    *(__half2*)(C16 + (size_t)(row0 + 8)*ldc + col) = h23;
                }
            }
        }
    }
}

// ---------------------------------------------------------------------------
// Fused attention: Q fp32, K/V fp16, 2 q-rows/warp pass, 2 CTAs/SM.
// ---------------------------------------------------------------------------
#define KP 72
#define VTP 258
#define ATT_K_OFF 0
#define ATT_VT_OFF 36864
#define ATT_PS_OFF 69888
#define ATT_QS_OFF 86272
#define ATT_BS_OFF 90368
#define ATT_SMEM 91392

__global__ __launch_bounds__(256, 2)
void attention_kernel(const float* __restrict__ qb,
                      const __half* __restrict__ kb,
                      const __half* __restrict__ vb,
                      const unsigned char* __restrict__ pad,
                      __half* __restrict__ ob)
{
    int bh = blockIdx.x;
    int b = bh >> 3, h = bh & 7;
    extern __shared__ unsigned char smb[];
    __half* Ks = (__half*)(smb + ATT_K_OFF);
    __half* Vt = (__half*)(smb + ATT_VT_OFF);
    float* Ps  = (float*)(smb + ATT_PS_OFF);
    float* Qs  = (float*)(smb + ATT_QS_OFF);
    float* Bsb = (float*)(smb + ATT_BS_OFF);

    int tid = threadIdx.x, lane = tid & 31, w = tid >> 5;
    const __half* kbase = kb + (size_t)(b*SS)*DD + h*DHH;
    const __half* vbase = vb + (size_t)(b*SS)*DD + h*DHH;

    for (int idx = tid; idx < 256*64; idx += 256) {
        int r = idx >> 6, c = idx & 63;
        Ks[r*KP + c]  = kbase[(size_t)r*DD + c];
        Vt[c*VTP + r] = vbase[(size_t)r*DD + c];
    }
    if (tid < 256) Bsb[tid] = pad[b*SS + tid] ? -1e9f : 0.f;
    __syncthreads();

    float* Pw0 = Ps + (2*w + 0)*256;
    float* Pw1 = Ps + (2*w + 1)*256;
    float* Qw = Qs + w*128;

    for (int qi = 2*w; qi < SS; qi += 16) {
        const float* q0 = qb + (size_t)(b*SS + qi)*DD + h*DHH;
        Qw[lane]           = q0[lane];
        Qw[lane + 32]      = q0[lane + 32];
        Qw[64 + lane]      = q0[DD + lane];
        Qw[64 + lane + 32] = q0[DD + lane + 32];
        __syncwarp();

        const float4* q4a = (const float4*)Qw;
        const float4* q4b = (const float4*)(Qw + 64);

        float s0[8], s1[8];
        float mx0 = -3.402823466e+38f, mx1 = -3.402823466e+38f;
        #pragma unroll
        for (int k8 = 0; k8 < 8; k8++) {
            int j = lane + 32*k8;
            const uint4* kr4 = (const uint4*)(Ks + j*KP);
            float a0 = 0.f, a1 = 0.f;
            #pragma unroll
            for (int d8 = 0; d8 < 8; d8++) {
                uint4 kv = kr4[d8];
                float2 f0 = __half22float2(*(__half2*)&kv.x);
                float2 f1 = __half22float2(*(__half2*)&kv.y);
                float2 f2 = __half22float2(*(__half2*)&kv.z);
                float2 f3 = __half22float2(*(__half2*)&kv.w);
                float4 qa0 = q4a[d8*2],   qa1 = q4a[d8*2+1];
                float4 qb0 = q4b[d8*2],   qb1 = q4b[d8*2+1];
                a0 += qa0.x*f0.x + qa0.y*f0.y + qa0.z*f1.x + qa0.w*f1.y
                    + qa1.x*f2.x + qa1.y*f2.y + qa1.z*f3.x + qa1.w*f3.y;
                a1 += qb0.x*f0.x + qb0.y*f0.y + qb0.z*f1.x + qb0.w*f1.y
                    + qb1.x*f2.x + qb1.y*f2.y + qb1.z*f3.x + qb1.w*f3.y;
            }
            float bias = Bsb[j];
            a0 = a0 * 0.125f + bias;
            a1 = a1 * 0.125f + bias;
            s0[k8] = a0; s1[k8] = a1;
            mx0 = fmaxf(mx0, a0); mx1 = fmaxf(mx1, a1);
        }
        for (int off = 16; off; off >>= 1) {
            mx0 = fmaxf(mx0, __shfl_xor_sync(0xffffffffu, mx0, off));
            mx1 = fmaxf(mx1, __shfl_xor_sync(0xffffffffu, mx1, off));
        }
        float sm0 = 0.f, sm1 = 0.f;
        #pragma unroll
        for (int k8 = 0; k8 < 8; k8++) {
            s0[k8] = __expf(s0[k8] - mx0); sm0 += s0[k8];
            s1[k8] = __expf(s1[k8] - mx1); sm1 += s1[k8];
        }
        for (int off = 16; off; off >>= 1) {
            sm0 += __shfl_xor_sync(0xffffffffu, sm0, off);
            sm1 += __shfl_xor_sync(0xffffffffu, sm1, off);
        }
        float i0 = 1.f / sm0, i1 = 1.f / sm1;
        #pragma unroll
        for (int k8 = 0; k8 < 8; k8++) {
            Pw0[lane + 32*k8] = s0[k8]*i0;
            Pw1[lane + 32*k8] = s1[k8]*i1;
        }
        __syncwarp();

        const __half2* vtA = (const __half2*)(Vt + (size_t)lane*VTP);
        const __half2* vtB = (const __half2*)(Vt + (size_t)(lane+32)*VTP);
        const float2* P02 = (const float2*)Pw0;
        const float2* P12 = (const float2*)Pw1;
        float o00 = 0.f, o01 = 0.f, o10 = 0.f, o11 = 0.f;
        for (int j2 = 0; j2 < 128; j2++) {
            float2 p0 = P02[j2];
            float2 p1 = P12[j2];
            float2 vA = __half22float2(vtA[j2]);
            float2 vB = __half22float2(vtB[j2]);
            o00 += p0.x*vA.x + p0.y*vA.y;
            o01 += p0.x*vB.x + p0.y*vB.y;
            o10 += p1.x*vA.x + p1.y*vA.y;
            o11 += p1.x*vB.x + p1.y*vB.y;
        }
        __half* orow = ob + (size_t)(b*SS + qi)*DD + h*DHH;
        orow[lane]           = __float2half_rn(o00);
        orow[lane + 32]      = __float2half_rn(o01);
        orow[DD + lane]      = __float2half_rn(o10);
        orow[DD + lane + 32] = __float2half_rn(o11);
        __syncwarp();
    }
}

// ---------------------------------------------------------------------------
// Residual add + LayerNorm
// ---------------------------------------------------------------------------
__global__ void ln_kernel(const float* __restrict__ x, const float* __restrict__ add,
                          const float* __restrict__ g, const float* __restrict__ bv,
                          float* __restrict__ out, __half* __restrict__ out16)
{
    int t = blockIdx.x;
    int tid = threadIdx.x;
    const float* xr = x   + (size_t)t*DD;
    const float* ar = add + (size_t)t*DD;
    float v[4];
    float s = 0.f, ss = 0.f;
    #pragma unroll
    for (int i = 0; i < 4; i++) {
        float u = xr[tid + 128*i] + ar[tid + 128*i];
        v[i] = u; s += u; ss += u*u;
    }
    for (int off = 16; off; off >>= 1) {
        s  += __shfl_xor_sync(0xffffffffu, s,  off);
        ss += __shfl_xor_sync(0xffffffffu, ss, off);
    }
    __shared__ float rs[4], rss[4];
    int w = tid >> 5, lane = tid & 31;
    if (lane == 0) { rs[w] = s; rss[w] = ss; }
    __syncthreads();
    s  = rs[0]+rs[1]+rs[2]+rs[3];
    ss = rss[0]+rss[1]+rss[2]+rss[3];
    float mean = s * (1.f/512.f);
    float var  = ss * (1.f/512.f) - mean*mean;
    float rstd = rsqrtf(var + 1e-5f);
    #pragma unroll
    for (int i = 0; i < 4; i++) {
        int c = tid + 128*i;
        float o = (v[i]-mean)*rstd*g[c] + bv[c];
        if (out)   out[(size_t)t*DD + c] = o;
        if (out16) out16[(size_t)t*DD + c] = __float2half_rn(o);
    }
}

// ---------------------------------------------------------------------------
// Launch
// ---------------------------------------------------------------------------
extern "C" void kernel_launch(void* const* d_in, const int* in_sizes, int n_in,
                              void* d_out, int out_size)
{
    const float* x_l  = (const float*)d_in[0];
    const float* x_r  = (const float*)d_in[1];
    const float* j_l  = (const float*)d_in[2];
    const float* j_r  = (const float*)d_in[3];
    const float* mcon = (const float*)d_in[4];
    const float* pc   = (const float*)d_in[5];
    const float* mask_l = (const float*)d_in[6];
    const float* mask_r = (const float*)d_in[7];
    const unsigned char* pad = (const unsigned char*)d_in[8];
    const float* W_fc_l = (const float*)d_in[9];
    const float* b_fc_l = (const float*)d_in[10];
    const float* W_fc_r = (const float*)d_in[11];
    const float* b_fc_r = (const float*)d_in[12];
    const float* Wq = (const float*)d_in[13];
    const float* Wk = (const float*)d_in[14];
    const float* Wv = (const float*)d_in[15];
    const float* Wo = (const float*)d_in[16];
    const float* W1 = (const float*)d_in[17];
    const float* b1 = (const float*)d_in[18];
    const float* W2 = (const float*)d_in[19];
    const float* b2 = (const float*)d_in[20];
    const float* ln1g = (const float*)d_in[21];
    const float* ln1b = (const float*)d_in[22];
    const float* ln2g = (const float*)d_in[23];
    const float* ln2b = (const float*)d_in[24];
    const float* W_out_l = (const float*)d_in[25];
    const float* b_out_l = (const float*)d_in[26];
    const float* W_out_r = (const float*)d_in[27];
    const float* b_out_r = (const float*)d_in[28];
    float* outp = (float*)d_out;

    float *px, *pq, *pproj, *px1, *pf;
    __half *pfl16, *pfr16, *px16, *pk16, *pv16, *pao16, *px116, *ph16, *px216;
    __half *wfcl, *wfcr, *wq16, *wk16, *wv16, *wo16, *w116, *w216, *pwl, *pwr;
    cudaGetSymbolAddress((void**)&px,    g_x);
    cudaGetSymbolAddress((void**)&pq,    g_q);
    cudaGetSymbolAddress((void**)&pproj, g_proj);
    cudaGetSymbolAddress((void**)&px1,   g_x1);
    cudaGetSymbolAddress((void**)&pf,    g_f);
    cudaGetSymbolAddress((void**)&pfl16, g_feat16_l);
    cudaGetSymbolAddress((void**)&pfr16, g_feat16_r);
    cudaGetSymbolAddress((void**)&px16,  g_x16);
    cudaGetSymbolAddress((void**)&pk16,  g_k16);
    cudaGetSymbolAddress((void**)&pv16,  g_v16);
    cudaGetSymbolAddress((void**)&pao16, g_ao16);
    cudaGetSymbolAddress((void**)&px116, g_x116);
    cudaGetSymbolAddress((void**)&ph16,  g_h16);
    cudaGetSymbolAddress((void**)&px216, g_x216);
    cudaGetSymbolAddress((void**)&wfcl,  g_wfc_l16);
    cudaGetSymbolAddress((void**)&wfcr,  g_wfc_r16);
    cudaGetSymbolAddress((void**)&wq16,  g_wq16);
    cudaGetSymbolAddress((void**)&wk16,  g_wk16);
    cudaGetSymbolAddress((void**)&wv16,  g_wv16);
    cudaGetSymbolAddress((void**)&wo16,  g_wo16);
    cudaGetSymbolAddress((void**)&w116,  g_w116);
    cudaGetSymbolAddress((void**)&w216,  g_w216);
    cudaGetSymbolAddress((void**)&pwl,   g_woutl16);
    cudaGetSymbolAddress((void**)&pwr,   g_woutr16);

    cudaFuncSetAttribute((const void*)tgemm<0,0,1>, cudaFuncAttributeMaxDynamicSharedMemorySize, TG_SMEM);
    cudaFuncSetAttribute((const void*)tgemm<0,0,3>, cudaFuncAttributeMaxDynamicSharedMemorySize, TG_SMEM);
    cudaFuncSetAttribute((const void*)tgemm<1,0,2>, cudaFuncAttributeMaxDynamicSharedMemorySize, TG_SMEM);
    cudaFuncSetAttribute((const void*)tgemm<2,1,2>, cudaFuncAttributeMaxDynamicSharedMemorySize, TG_SMEM);
    cudaFuncSetAttribute(attention_kernel,
                         cudaFuncAttributeMaxDynamicSharedMemorySize, ATT_SMEM);

    EpiParams none = {nullptr, nullptr, nullptr, 0, 0, 0};

    // 0. weight conversion + head-weight padding
    {
        CvtJobs cj;
        cj.src[0] = W_fc_l; cj.dst[0] = wfcl; cj.n4[0] = (CAT*DD)/4;
        cj.src[1] = W_fc_r; cj.dst[1] = wfcr; cj.n4[1] = (CAT*DD)/4;
        cj.src[2] = Wq;     cj.dst[2] = wq16; cj.n4[2] = (DD*DD)/4;
        cj.src[3] = Wk;     cj.dst[3] = wk16; cj.n4[3] = (DD*DD)/4;
        cj.src[4] = Wv;     cj.dst[4] = wv16; cj.n4[4] = (DD*DD)/4;
        cj.src[5] = Wo;     cj.dst[5] = wo16; cj.n4[5] = (DD*DD)/4;
        cj.src[6] = W1;     cj.dst[6] = w116; cj.n4[6] = (DD*DFF)/4;
        cj.src[7] = W2;     cj.dst[7] = w216; cj.n4[7] = (DFF*DD)/4;
        cvt_weights_kernel<<<1024, 256>>>(cj);
    }
    pad_wout_kernel<<<256, 256>>>(W_out_l, W_out_r, pwl, pwr);

    // 1. features (fp16)
    build_features_kernel<<<ROWS, 256>>>(x_l, x_r, j_l, j_r, mcon, pc, pfl16, pfr16);

    // 2. fc projections (merged l+r)
    {
        Jobs<2> jb;
        jb.j[0] = { pfl16, wfcl, px,      px16,      {b_fc_l, mask_l, pad, 0, 0, 0} };
        jb.j[1] = { pfr16, wfcr, px + DD, px16 + DD, {b_fc_r, mask_r, pad, 1, 0, 0} };
        tgemm<1,0,2><<<dim3(8,64,2), 128, TG_SMEM>>>(jb, CATP, DD, 2*DD, ROWS, DD, CAT);
    }

    // 3. QKV (merged)
    {
        Jobs<3> jb;
        jb.j[0] = { px16, wq16, pq,      nullptr, none };
        jb.j[1] = { px16, wk16, nullptr, pk16,    none };
        jb.j[2] = { px16, wv16, nullptr, pv16,    none };
        tgemm<0,0,3><<<dim3(8,128,3), 128, TG_SMEM>>>(jb, DD, DD, DD, TROWS, DD, DD);
    }

    // 4. attention
    attention_kernel<<<BB*HH, 256, ATT_SMEM>>>(pq, pk16, pv16, pad, pao16);

    // 5. Wo + LN1
    {
        Jobs<1> jb; jb.j[0] = { pao16, wo16, pproj, nullptr, none };
        tgemm<0,0,1><<<dim3(8,128,1), 128, TG_SMEM>>>(jb, DD, DD, DD, TROWS, DD, DD);
    }
    ln_kernel<<<TROWS, 128>>>(px, pproj, ln1g, ln1b, px1, px116);

    // 6. FFN + LN2
    {
        Jobs<1> jb; jb.j[0] = { px116, w116, nullptr, ph16, {b1, nullptr, nullptr, 0, 1, 0} };
        tgemm<0,0,1><<<dim3(32,128,1), 128, TG_SMEM>>>(jb, DD, DFF, DFF, TROWS, DFF, DD);
    }
    {
        Jobs<1> jb; jb.j[0] = { ph16, w216, pf, nullptr, {b2, nullptr, nullptr, 0, 0, 0} };
        tgemm<0,0,1><<<dim3(8,128,1), 128, TG_SMEM>>>(jb, DFF, DD, DD, TROWS, DD, DFF);
    }
    ln_kernel<<<TROWS, 128>>>(px1, pf, ln2g, ln2b, nullptr, px216);

    // 7. output heads (merged l+r, guarded cols)
    {
        Jobs<2> jb;
        jb.j[0] = { px216,      pwl, outp,                 nullptr, {b_out_l, mask_l, pad, 0, 0, HAND_DIM} };
        jb.j[1] = { px216 + DD, pwr, outp + ROWS*HAND_DIM, nullptr, {b_out_r, mask_r, pad, 1, 0, HAND_DIM} };
        tgemm<2,1,2><<<dim3(2,64,2), 128, TG_SMEM>>>(jb, 2*DD, 128, HAND_DIM, ROWS, 128, DD);
    }
}

// round 14
// speedup vs baseline: 1.0138x; 1.0138x over previous
#include <cuda_runtime.h>
#include <cuda_fp16.h>
#include <math.h>

// ---------------------------------------------------------------------------
// Shapes
// ---------------------------------------------------------------------------
#define BB 32
#define LL 128
#define NN 512
#define JJ 21
#define HAND_DIM 99
#define DD 512
#define HH 8
#define DHH 64
#define DFF 2048
#define CAT 1249
#define CATP 1280
#define SS 256
#define ROWS 4096
#define TROWS 8192

#define F_X 0
#define F_J 99
#define F_MC 162
#define F_PCN 674
#define F_ATT 1186

// ---------------------------------------------------------------------------
// Scratch
// ---------------------------------------------------------------------------
__device__ float g_x   [TROWS * DD];
__device__ float g_q   [TROWS * DD];
__device__ float g_proj[TROWS * DD];
__device__ float g_x1  [TROWS * DD];
__device__ float g_f   [TROWS * DD];

__device__ __align__(16) __half g_feat16_l[ROWS * CATP];
__device__ __align__(16) __half g_feat16_r[ROWS * CATP];
__device__ __align__(16) __half g_x16  [TROWS * DD];
__device__ __align__(16) __half g_k16  [TROWS * DD];
__device__ __align__(16) __half g_v16  [TROWS * DD];
__device__ __align__(16) __half g_ao16 [TROWS * DD];
__device__ __align__(16) __half g_x116 [TROWS * DD];
__device__ __align__(16) __half g_h16  [TROWS * DFF];
__device__ __align__(16) __half g_x216 [TROWS * DD];

__device__ __align__(16) __half g_wfc_l16[CAT * DD];
__device__ __align__(16) __half g_wfc_r16[CAT * DD];
__device__ __align__(16) __half g_wq16 [DD * DD];
__device__ __align__(16) __half g_wk16 [DD * DD];
__device__ __align__(16) __half g_wv16 [DD * DD];
__device__ __align__(16) __half g_wo16 [DD * DD];
__device__ __align__(16) __half g_w116 [DD * DFF];
__device__ __align__(16) __half g_w216 [DFF * DD];
__device__ __align__(16) __half g_woutl16[DD * 128];
__device__ __align__(16) __half g_woutr16[DD * 128];

// ---------------------------------------------------------------------------
// Weight conversion
// ---------------------------------------------------------------------------
struct CvtJobs {
    const float* src[8];
    __half* dst[8];
    int n4[8];
};
__global__ void cvt_weights_kernel(CvtJobs cj)
{
    int gid = blockIdx.x * blockDim.x + threadIdx.x;
    int stride = gridDim.x * blockDim.x;
    #pragma unroll
    for (int j = 0; j < 8; j++) {
        const float4* s = (const float4*)cj.src[j];
        __half2* d = (__half2*)cj.dst[j];
        int n4 = cj.n4[j];
        for (int i = gid; i < n4; i += stride) {
            float4 v = s[i];
            d[2*i]   = __floats2half2_rn(v.x, v.y);
            d[2*i+1] = __floats2half2_rn(v.z, v.w);
        }
    }
}

__global__ void pad_wout_kernel(const float* __restrict__ Wl, const float* __restrict__ Wr,
                                __half* __restrict__ dl, __half* __restrict__ dr)
{
    int idx = blockIdx.x * 256 + threadIdx.x;
    int row = idx >> 7, col = idx & 127;
    float vl = (col < HAND_DIM) ? Wl[row*HAND_DIM + col] : 0.f;
    float vr = (col < HAND_DIM) ? Wr[row*HAND_DIM + col] : 0.f;
    dl[idx] = __float2half_rn(vl);
    dr[idx] = __float2half_rn(vr);
}

// ---------------------------------------------------------------------------
// Feature build -> fp16
// ---------------------------------------------------------------------------
__global__ void build_features_kernel(
    const float* __restrict__ x_l, const float* __restrict__ x_r,
    const float* __restrict__ j_l, const float* __restrict__ j_r,
    const float* __restrict__ m_contact, const float* __restrict__ pc,
    __half* __restrict__ feat_l, __half* __restrict__ feat_r)
{
    int m = blockIdx.x;
    int b = m >> 7;
    __shared__ float px[NN], py[NN], pz[NN];
    int tid = threadIdx.x;

    const float* pcb = pc + (size_t)m * NN * 3;
    for (int n = tid; n < NN; n += 256) {
        px[n] = pcb[n*3+0]; py[n] = pcb[n*3+1]; pz[n] = pcb[n*3+2];
    }
    __syncthreads();

    __half* fl = feat_l + (size_t)m * CATP;
    __half* fr = feat_r + (size_t)m * CATP;

    for (int i = tid; i < HAND_DIM; i += 256) {
        fl[F_X+i] = __float2half_rn(x_l[(size_t)m*HAND_DIM + i]);
        fr[F_X+i] = __float2half_rn(x_r[(size_t)m*HAND_DIM + i]);
    }
    for (int i = tid; i < JJ*3; i += 256) {
        fl[F_J+i] = __float2half_rn(j_l[(size_t)m*JJ*3 + i]);
        fr[F_J+i] = __float2half_rn(j_r[(size_t)m*JJ*3 + i]);
    }
    for (int n = tid; n < NN; n += 256) {
        __half mc = __float2half_rn(m_contact[b*NN + n]);
        fl[F_MC+n] = mc; fr[F_MC+n] = mc;
        __half nm = __float2half_rn(sqrtf(px[n]*px[n] + py[n]*py[n] + pz[n]*pz[n]));
        fl[F_PCN+n] = nm; fr[F_PCN+n] = nm;
    }
    __half z = __float2half_rn(0.f);
    for (int i = CAT + tid; i < CATP; i += 256) { fl[i] = z; fr[i] = z; }

    int w = tid >> 5, lane = tid & 31;
    for (int task = w; task < 2*JJ; task += 8) {
        int hand = task / JJ, joint = task % JJ;
        const float* jb = (hand == 0 ? j_l : j_r) + ((size_t)m*JJ + joint)*3;
        float jx = jb[0], jy = jb[1], jz = jb[2];
        float best = 3.402823466e+38f; int bi = 0;
        for (int n = lane; n < NN; n += 32) {
            float dx = jx - px[n], dy = jy - py[n], dz = jz - pz[n];
            float d2 = dx*dx + dy*dy + dz*dz;
            if (d2 < best) { best = d2; bi = n; }
        }
        for (int off = 16; off; off >>= 1) {
            float ob = __shfl_xor_sync(0xffffffffu, best, off);
            int   oi = __shfl_xor_sync(0xffffffffu, bi, off);
            if (ob < best || (ob == best && oi < bi)) { best = ob; bi = oi; }
        }
        if (lane == 0) {
            float dx = jx - px[bi], dy = jy - py[bi], dz = jz - pz[bi];
            __half* f = (hand == 0 ? fl : fr);
            f[F_ATT + joint*3 + 0] = __float2half_rn(expf(-50.f * dx * dx));
            f[F_ATT + joint*3 + 1] = __float2half_rn(expf(-50.f * dy * dy));
            f[F_ATT + joint*3 + 2] = __float2half_rn(expf(-50.f * dz * dz));
        }
    }
}

// ---------------------------------------------------------------------------
// Epilogues
// ---------------------------------------------------------------------------
struct EpiParams {
    const float* bias;
    const float* mask;
    const unsigned char* pad;
    int hand;
    int relu;
    int nreal;
};

#define LN10000 9.2103403719761827f

template<int EPI>
__device__ __forceinline__ float apply_epi(float v, int row, int col, const EpiParams& ep)
{
    if (EPI == 0) {
        if (ep.bias) v += ep.bias[col];
        if (ep.relu) v = fmaxf(v, 0.f);
    } else if (EPI == 1) {
        int l = row & 127;
        int ii = col >> 1;
        float freq = expf(-LN10000 * (float)ii * (1.f/256.f));
        float angF = (float)l * freq;
        float angA = (float)ep.hand * freq;
        float pe = (col & 1) ? (cosf(angF) + cosf(angA))
                             : (sinf(angF) + sinf(angA));
        float mv = ep.mask[row] * (ep.pad[2*row + ep.hand] ? 0.f : 1.f);
        v = (v + ep.bias[col] + pe) * mv;
    } else { // EPI == 2
        float mv = ep.mask[row] * (ep.pad[2*row + ep.hand] ? 0.f : 1.f);
        v = (v + ep.bias[col]) * mv;
    }
    return v;
}

// ---------------------------------------------------------------------------
// Multi-job single-pass fp16 GEMM, 2-stage cp.async (R12 proven layout).
// 128 threads, tile 64x64, BK=32, 4 warps (2x2), 6 CTAs/SM.
// ---------------------------------------------------------------------------
struct Job { const __half* A; const __half* B; float* C; __half* C16; EpiParams ep; };
template<int NJ> struct Jobs { Job j[NJ]; };

#define PA 80
#define PB 144
#define A_BYTES (64*PA)
#define B_BYTES (32*PB)
#define OFF_AH 0
#define OFF_BH (A_BYTES)
#define BUF_BYTES (A_BYTES + B_BYTES)     // 9728
#define TG_SMEM (2*BUF_BYTES)             // 19456

__device__ __forceinline__ unsigned smem_u32(const void* p) {
    return (unsigned)__cvta_generic_to_shared(p);
}
__device__ __forceinline__ void ldsm4(unsigned* r, unsigned addr) {
    asm volatile("ldmatrix.sync.aligned.m8n8.x4.shared.b16 {%0,%1,%2,%3}, [%4];"
        : "=r"(r[0]), "=r"(r[1]), "=r"(r[2]), "=r"(r[3]) : "r"(addr));
}
__device__ __forceinline__ void ldsm4t(unsigned* r, unsigned addr) {
    asm volatile("ldmatrix.sync.aligned.m8n8.x4.trans.shared.b16 {%0,%1,%2,%3}, [%4];"
        : "=r"(r[0]), "=r"(r[1]), "=r"(r[2]), "=r"(r[3]) : "r"(addr));
}
__device__ __forceinline__ void mma16816(float* c, const unsigned* a, unsigned b0, unsigned b1) {
    asm volatile(
        "mma.sync.aligned.m16n8k16.row.col.f32.f16.f16.f32 "
        "{%0,%1,%2,%3}, {%4,%5,%6,%7}, {%8,%9}, {%0,%1,%2,%3};"
        : "+f"(c[0]), "+f"(c[1]), "+f"(c[2]), "+f"(c[3])
        : "r"(a[0]), "r"(a[1]), "r"(a[2]), "r"(a[3]), "r"(b0), "r"(b1));
}
__device__ __forceinline__ void cp16(unsigned dst, const void* src, bool full) {
    int sz = full ? 16 : 0;
    asm volatile("cp.async.cg.shared.global [%0], [%1], 16, %2;"
                 :: "r"(dst), "l"(src), "r"(sz) : "memory");
}
__device__ __forceinline__ void cp_commit() {
    asm volatile("cp.async.commit_group;" ::: "memory");
}
template<int N> __device__ __forceinline__ void cp_wait() {
    asm volatile("cp.async.wait_group %0;" :: "n"(N) : "memory");
}

template<int EPI, int GUARD, int NJ>
__global__ __launch_bounds__(128, 6)
void tgemm(Jobs<NJ> jobs, int lda, int ldb, int ldc, int M, int N, int Kreal)
{
    const Job& jb = jobs.j[blockIdx.z];
    const __half* __restrict__ A = jb.A;
    const __half* __restrict__ B = jb.B;
    float* __restrict__ C = jb.C;
    __half* __restrict__ C16 = jb.C16;
    EpiParams ep = jb.ep;

    extern __shared__ unsigned char smraw[];
    unsigned sbase = smem_u32(smraw);
    int tid = threadIdx.x, lane = tid & 31, wid = tid >> 5;
    int warp_m = wid & 1, warp_n = wid >> 1;
    int m0 = blockIdx.y * 64, n0 = blockIdx.x * 64;
    int g = lane >> 2, t = lane & 3;

    float acc[2][4][4];
    #pragma unroll
    for (int i = 0; i < 2; i++)
        #pragma unroll
        for (int j = 0; j < 4; j++)
            #pragma unroll
            for (int e = 0; e < 4; e++) acc[i][j][e] = 0.f;

    int aRow = lane & 15;
    int aKof = ((lane >> 4) & 1) * 8;
    int bRow = lane & 15;
    int bNof = ((lane >> 4) & 1) * 8;

    int nk = (Kreal + 31) >> 5;

    auto prefetch = [&](int kt) {
        int k0 = kt * 32;
        unsigned bufb = sbase + (kt & 1) * BUF_BYTES;
        #pragma unroll
        for (int i = 0; i < 2; i++) {
            int c = tid + 128*i;
            int r = c >> 2, col8 = (c & 3) * 8;
            cp16(bufb + OFF_AH + r*PA + col8*2,
                 A + (size_t)(m0 + r)*lda + k0 + col8, true);
        }
        #pragma unroll
        for (int i = 0; i < 2; i++) {
            int c = tid + 128*i;
            int r = c >> 3, col8 = (c & 7) * 8;
            int k = k0 + r;
            int ksafe = (k < Kreal) ? k : (Kreal - 1);
            cp16(bufb + OFF_BH + r*PB + col8*2,
                 B + (size_t)ksafe*ldb + n0 + col8, k < Kreal);
        }
        cp_commit();
    };

    prefetch(0);

    for (int kt = 0; kt < nk; kt++) {
        if (kt + 1 < nk) { prefetch(kt + 1); cp_wait<1>(); }
        else             { cp_wait<0>(); }
        __syncthreads();

        unsigned base = sbase + (kt & 1) * BUF_BYTES;
        #pragma unroll
        for (int ks = 0; ks < 2; ks++) {
            unsigned aAddrBase = base + (ks*16 + aKof) * 2;
            unsigned bAddrBase = base + (ks*16 + bRow) * PB;

            unsigned ah[2][4], bh[2][4];
            #pragma unroll
            for (int mt = 0; mt < 2; mt++)
                ldsm4(ah[mt], aAddrBase + OFF_AH + (warp_m*32 + mt*16 + aRow)*PA);
            #pragma unroll
            for (int np = 0; np < 2; np++)
                ldsm4t(bh[np], bAddrBase + OFF_BH + (warp_n*32 + np*16 + bNof)*2);

            #pragma unroll
            for (int mt = 0; mt < 2; mt++)
                #pragma unroll
                for (int nt = 0; nt < 4; nt++)
                    mma16816(acc[mt][nt], ah[mt], bh[nt>>1][(nt&1)*2], bh[nt>>1][(nt&1)*2+1]);
        }
        __syncthreads();
    }

    #pragma unroll
    for (int mt = 0; mt < 2; mt++) {
        int row0 = m0 + warp_m*32 + mt*16 + g;
        #pragma unroll
        for (int nt = 0; nt < 4; nt++) {
            int col = n0 + warp_n*32 + nt*8 + t*2;
            float* c = acc[mt][nt];
            float v0 = apply_epi<EPI>(c[0], row0,     col,     ep);
            float v1 = apply_epi<EPI>(c[1], row0,     col + 1, ep);
            float v2 = apply_epi<EPI>(c[2], row0 + 8, col,     ep);
            float v3 = apply_epi<EPI>(c[3], row0 + 8, col + 1, ep);
            if (GUARD) {
                if (C) {
                    if (col < ep.nreal)     C[(size_t)row0*ldc + col]         = v0;
                    if (col + 1 < ep.nreal) C[(size_t)row0*ldc + col + 1]     = v1;
                    if (col < ep.nreal)     C[(size_t)(row0+8)*ldc + col]     = v2;
                    if (col + 1 < ep.nreal) C[(size_t)(row0+8)*ldc + col + 1] = v3;
                }
            } else {
                if (C) {
                    *(float2*)(C + (size_t)row0*ldc + col)       = make_float2(v0, v1);
                    *(float2*)(C + (size_t)(row0 + 8)*ldc + col) = make_float2(v2, v3);
                }
                if (C16) {
                    __half2 h01 = __floats2half2_rn(v0, v1);
                    __half2 h23 = __floats2half2_rn(v2, v3);
                    *(__half2*)(C16 + (size_t)row0*ldc + col)       = h01;
                    *(__half2*)(C16 + (size_t)(row0 + 8)*ldc + col) = h23;
                }
            }
        }
    }
}

// ---------------------------------------------------------------------------
// Fused attention, q-split x2: grid = BB*HH*2; each CTA does 128 q-rows.
// Q fp32, K/V fp16, 2 q-rows/warp pass, 2 CTAs/SM.
// ---------------------------------------------------------------------------
#define KP 72
#define VTP 258
#define ATT_K_OFF 0
#define ATT_VT_OFF 36864
#define ATT_PS_OFF 69888
#define ATT_QS_OFF 86272
#define ATT_BS_OFF 90368
#define ATT_SMEM 91392

__global__ __launch_bounds__(256, 2)
void attention_kernel(const float* __restrict__ qb,
                      const __half* __restrict__ kb,
                      const __half* __restrict__ vb,
                      const unsigned char* __restrict__ pad,
                      __half* __restrict__ ob)
{
    int blk = blockIdx.x;
    int bh = blk >> 1;              // b*8 + h
    int qhalf = blk & 1;
    int b = bh >> 3, h = bh & 7;
    extern __shared__ unsigned char smb[];
    __half* Ks = (__half*)(smb + ATT_K_OFF);
    __half* Vt = (__half*)(smb + ATT_VT_OFF);
    float* Ps  = (float*)(smb + ATT_PS_OFF);
    float* Qs  = (float*)(smb + ATT_QS_OFF);
    float* Bsb = (float*)(smb + ATT_BS_OFF);

    int tid = threadIdx.x, lane = tid & 31, w = tid >> 5;
    const __half* kbase = kb + (size_t)(b*SS)*DD + h*DHH;
    const __half* vbase = vb + (size_t)(b*SS)*DD + h*DHH;

    for (int idx = tid; idx < 256*64; idx += 256) {
        int r = idx >> 6, c = idx & 63;
        Ks[r*KP + c]  = kbase[(size_t)r*DD + c];
        Vt[c*VTP + r] = vbase[(size_t)r*DD + c];
    }
    if (tid < 256) Bsb[tid] = pad[b*SS + tid] ? -1e9f : 0.f;
    __syncthreads();

    float* Pw0 = Ps + (2*w + 0)*256;
    float* Pw1 = Ps + (2*w + 1)*256;
    float* Qw = Qs + w*128;

    int q0base = qhalf * 128;
    for (int qi = q0base + 2*w; qi < q0base + 128; qi += 16) {
        const float* q0 = qb + (size_t)(b*SS + qi)*DD + h*DHH;
        Qw[lane]           = q0[lane];
        Qw[lane + 32]      = q0[lane + 32];
        Qw[64 + lane]      = q0[DD + lane];
        Qw[64 + lane + 32] = q0[DD + lane + 32];
        __syncwarp();

        const float4* q4a = (const float4*)Qw;
        const float4* q4b = (const float4*)(Qw + 64);

        float s0[8], s1[8];
        float mx0 = -3.402823466e+38f, mx1 = -3.402823466e+38f;
        #pragma unroll
        for (int k8 = 0; k8 < 8; k8++) {
            int j = lane + 32*k8;
            const uint4* kr4 = (const uint4*)(Ks + j*KP);
            float a0 = 0.f, a1 = 0.f;
            #pragma unroll
            for (int d8 = 0; d8 < 8; d8++) {
                uint4 kv = kr4[d8];
                float2 f0 = __half22float2(*(__half2*)&kv.x);
                float2 f1 = __half22float2(*(__half2*)&kv.y);
                float2 f2 = __half22float2(*(__half2*)&kv.z);
                float2 f3 = __half22float2(*(__half2*)&kv.w);
                float4 qa0 = q4a[d8*2],   qa1 = q4a[d8*2+1];
                float4 qb0 = q4b[d8*2],   qb1 = q4b[d8*2+1];
                a0 += qa0.x*f0.x + qa0.y*f0.y + qa0.z*f1.x + qa0.w*f1.y
                    + qa1.x*f2.x + qa1.y*f2.y + qa1.z*f3.x + qa1.w*f3.y;
                a1 += qb0.x*f0.x + qb0.y*f0.y + qb0.z*f1.x + qb0.w*f1.y
                    + qb1.x*f2.x + qb1.y*f2.y + qb1.z*f3.x + qb1.w*f3.y;
            }
            float bias = Bsb[j];
            a0 = a0 * 0.125f + bias;
            a1 = a1 * 0.125f + bias;
            s0[k8] = a0; s1[k8] = a1;
            mx0 = fmaxf(mx0, a0); mx1 = fmaxf(mx1, a1);
        }
        for (int off = 16; off; off >>= 1) {
            mx0 = fmaxf(mx0, __shfl_xor_sync(0xffffffffu, mx0, off));
            mx1 = fmaxf(mx1, __shfl_xor_sync(0xffffffffu, mx1, off));
        }
        float sm0 = 0.f, sm1 = 0.f;
        #pragma unroll
        for (int k8 = 0; k8 < 8; k8++) {
            s0[k8] = __expf(s0[k8] - mx0); sm0 += s0[k8];
            s1[k8] = __expf(s1[k8] - mx1); sm1 += s1[k8];
        }
        for (int off = 16; off; off >>= 1) {
            sm0 += __shfl_xor_sync(0xffffffffu, sm0, off);
            sm1 += __shfl_xor_sync(0xffffffffu, sm1, off);
        }
        float i0 = 1.f / sm0, i1 = 1.f / sm1;
        #pragma unroll
        for (int k8 = 0; k8 < 8; k8++) {
            Pw0[lane + 32*k8] = s0[k8]*i0;
            Pw1[lane + 32*k8] = s1[k8]*i1;
        }
        __syncwarp();

        const __half2* vtA = (const __half2*)(Vt + (size_t)lane*VTP);
        const __half2* vtB = (const __half2*)(Vt + (size_t)(lane+32)*VTP);
        const float2* P02 = (const float2*)Pw0;
        const float2* P12 = (const float2*)Pw1;
        float o00 = 0.f, o01 = 0.f, o10 = 0.f, o11 = 0.f;
        for (int j2 = 0; j2 < 128; j2++) {
            float2 p0 = P02[j2];
            float2 p1 = P12[j2];
            float2 vA = __half22float2(vtA[j2]);
            float2 vB = __half22float2(vtB[j2]);
            o00 += p0.x*vA.x + p0.y*vA.y;
            o01 += p0.x*vB.x + p0.y*vB.y;
            o10 += p1.x*vA.x + p1.y*vA.y;
            o11 += p1.x*vB.x + p1.y*vB.y;
        }
        __half* orow = ob + (size_t)(b*SS + qi)*DD + h*DHH;
        orow[lane]           = __float2half_rn(o00);
        orow[lane + 32]      = __float2half_rn(o01);
        orow[DD + lane]      = __float2half_rn(o10);
        orow[DD + lane + 32] = __float2half_rn(o11);
        __syncwarp();
    }
}

// ---------------------------------------------------------------------------
// Residual add + LayerNorm
// ---------------------------------------------------------------------------
__global__ void ln_kernel(const float* __restrict__ x, const float* __restrict__ add,
                          const float* __restrict__ g, const float* __restrict__ bv,
                          float* __restrict__ out, __half* __restrict__ out16)
{
    int t = blockIdx.x;
    int tid = threadIdx.x;
    const float* xr = x   + (size_t)t*DD;
    const float* ar = add + (size_t)t*DD;
    float v[4];
    float s = 0.f, ss = 0.f;
    #pragma unroll
    for (int i = 0; i < 4; i++) {
        float u = xr[tid + 128*i] + ar[tid + 128*i];
        v[i] = u; s += u; ss += u*u;
    }
    for (int off = 16; off; off >>= 1) {
        s  += __shfl_xor_sync(0xffffffffu, s,  off);
        ss += __shfl_xor_sync(0xffffffffu, ss, off);
    }
    __shared__ float rs[4], rss[4];
    int w = tid >> 5, lane = tid & 31;
    if (lane == 0) { rs[w] = s; rss[w] = ss; }
    __syncthreads();
    s  = rs[0]+rs[1]+rs[2]+rs[3];
    ss = rss[0]+rss[1]+rss[2]+rss[3];
    float mean = s * (1.f/512.f);
    float var  = ss * (1.f/512.f) - mean*mean;
    float rstd = rsqrtf(var + 1e-5f);
    #pragma unroll
    for (int i = 0; i < 4; i++) {
        int c = tid + 128*i;
        float o = (v[i]-mean)*rstd*g[c] + bv[c];
        if (out)   out[(size_t)t*DD + c] = o;
        if (out16) out16[(size_t)t*DD + c] = __float2half_rn(o);
    }
}

// ---------------------------------------------------------------------------
// Launch
// ---------------------------------------------------------------------------
extern "C" void kernel_launch(void* const* d_in, const int* in_sizes, int n_in,
                              void* d_out, int out_size)
{
    const float* x_l  = (const float*)d_in[0];
    const float* x_r  = (const float*)d_in[1];
    const float* j_l  = (const float*)d_in[2];
    const float* j_r  = (const float*)d_in[3];
    const float* mcon = (const float*)d_in[4];
    const float* pc   = (const float*)d_in[5];
    const float* mask_l = (const float*)d_in[6];
    const float* mask_r = (const float*)d_in[7];
    const unsigned char* pad = (const unsigned char*)d_in[8];
    const float* W_fc_l = (const float*)d_in[9];
    const float* b_fc_l = (const float*)d_in[10];
    const float* W_fc_r = (const float*)d_in[11];
    const float* b_fc_r = (const float*)d_in[12];
    const float* Wq = (const float*)d_in[13];
    const float* Wk = (const float*)d_in[14];
    const float* Wv = (const float*)d_in[15];
    const float* Wo = (const float*)d_in[16];
    const float* W1 = (const float*)d_in[17];
    const float* b1 = (const float*)d_in[18];
    const float* W2 = (const float*)d_in[19];
    const float* b2 = (const float*)d_in[20];
    const float* ln1g = (const float*)d_in[21];
    const float* ln1b = (const float*)d_in[22];
    const float* ln2g = (const float*)d_in[23];
    const float* ln2b = (const float*)d_in[24];
    const float* W_out_l = (const float*)d_in[25];
    const float* b_out_l = (const float*)d_in[26];
    const float* W_out_r = (const float*)d_in[27];
    const float* b_out_r = (const float*)d_in[28];
    float* outp = (float*)d_out;

    float *px, *pq, *pproj, *px1, *pf;
    __half *pfl16, *pfr16, *px16, *pk16, *pv16, *pao16, *px116, *ph16, *px216;
    __half *wfcl, *wfcr, *wq16, *wk16, *wv16, *wo16, *w116, *w216, *pwl, *pwr;
    cudaGetSymbolAddress((void**)&px,    g_x);
    cudaGetSymbolAddress((void**)&pq,    g_q);
    cudaGetSymbolAddress((void**)&pproj, g_proj);
    cudaGetSymbolAddress((void**)&px1,   g_x1);
    cudaGetSymbolAddress((void**)&pf,    g_f);
    cudaGetSymbolAddress((void**)&pfl16, g_feat16_l);
    cudaGetSymbolAddress((void**)&pfr16, g_feat16_r);
    cudaGetSymbolAddress((void**)&px16,  g_x16);
    cudaGetSymbolAddress((void**)&pk16,  g_k16);
    cudaGetSymbolAddress((void**)&pv16,  g_v16);
    cudaGetSymbolAddress((void**)&pao16, g_ao16);
    cudaGetSymbolAddress((void**)&px116, g_x116);
    cudaGetSymbolAddress((void**)&ph16,  g_h16);
    cudaGetSymbolAddress((void**)&px216, g_x216);
    cudaGetSymbolAddress((void**)&wfcl,  g_wfc_l16);
    cudaGetSymbolAddress((void**)&wfcr,  g_wfc_r16);
    cudaGetSymbolAddress((void**)&wq16,  g_wq16);
    cudaGetSymbolAddress((void**)&wk16,  g_wk16);
    cudaGetSymbolAddress((void**)&wv16,  g_wv16);
    cudaGetSymbolAddress((void**)&wo16,  g_wo16);
    cudaGetSymbolAddress((void**)&w116,  g_w116);
    cudaGetSymbolAddress((void**)&w216,  g_w216);
    cudaGetSymbolAddress((void**)&pwl,   g_woutl16);
    cudaGetSymbolAddress((void**)&pwr,   g_woutr16);

    cudaFuncSetAttribute((const void*)tgemm<0,0,1>, cudaFuncAttributeMaxDynamicSharedMemorySize, TG_SMEM);
    cudaFuncSetAttribute((const void*)tgemm<0,0,3>, cudaFuncAttributeMaxDynamicSharedMemorySize, TG_SMEM);
    cudaFuncSetAttribute((const void*)tgemm<1,0,2>, cudaFuncAttributeMaxDynamicSharedMemorySize, TG_SMEM);
    cudaFuncSetAttribute((const void*)tgemm<2,1,2>, cudaFuncAttributeMaxDynamicSharedMemorySize, TG_SMEM);
    cudaFuncSetAttribute(attention_kernel,
                         cudaFuncAttributeMaxDynamicSharedMemorySize, ATT_SMEM);

    EpiParams none = {nullptr, nullptr, nullptr, 0, 0, 0};

    // 0. weight conversion + head-weight padding
    {
        CvtJobs cj;
        cj.src[0] = W_fc_l; cj.dst[0] = wfcl; cj.n4[0] = (CAT*DD)/4;
        cj.src[1] = W_fc_r; cj.dst[1] = wfcr; cj.n4[1] = (CAT*DD)/4;
        cj.src[2] = Wq;     cj.dst[2] = wq16; cj.n4[2] = (DD*DD)/4;
        cj.src[3] = Wk;     cj.dst[3] = wk16; cj.n4[3] = (DD*DD)/4;
        cj.src[4] = Wv;     cj.dst[4] = wv16; cj.n4[4] = (DD*DD)/4;
        cj.src[5] = Wo;     cj.dst[5] = wo16; cj.n4[5] = (DD*DD)/4;
        cj.src[6] = W1;     cj.dst[6] = w116; cj.n4[6] = (DD*DFF)/4;
        cj.src[7] = W2;     cj.dst[7] = w216; cj.n4[7] = (DFF*DD)/4;
        cvt_weights_kernel<<<1024, 256>>>(cj);
    }
    pad_wout_kernel<<<256, 256>>>(W_out_l, W_out_r, pwl, pwr);

    // 1. features (fp16)
    build_features_kernel<<<ROWS, 256>>>(x_l, x_r, j_l, j_r, mcon, pc, pfl16, pfr16);

    // 2. fc projections (merged l+r)
    {
        Jobs<2> jb;
        jb.j[0] = { pfl16, wfcl, px,      px16,      {b_fc_l, mask_l, pad, 0, 0, 0} };
        jb.j[1] = { pfr16, wfcr, px + DD, px16 + DD, {b_fc_r, mask_r, pad, 1, 0, 0} };
        tgemm<1,0,2><<<dim3(8,64,2), 128, TG_SMEM>>>(jb, CATP, DD, 2*DD, ROWS, DD, CAT);
    }

    // 3. QKV (merged)
    {
        Jobs<3> jb;
        jb.j[0] = { px16, wq16, pq,      nullptr, none };
        jb.j[1] = { px16, wk16, nullptr, pk16,    none };
        jb.j[2] = { px16, wv16, nullptr, pv16,    none };
        tgemm<0,0,3><<<dim3(8,128,3), 128, TG_SMEM>>>(jb, DD, DD, DD, TROWS, DD, DD);
    }

    // 4. attention (q-split x2)
    attention_kernel<<<BB*HH*2, 256, ATT_SMEM>>>(pq, pk16, pv16, pad, pao16);

    // 5. Wo + LN1
    {
        Jobs<1> jb; jb.j[0] = { pao16, wo16, pproj, nullptr, none };
        tgemm<0,0,1><<<dim3(8,128,1), 128, TG_SMEM>>>(jb, DD, DD, DD, TROWS, DD, DD);
    }
    ln_kernel<<<TROWS, 128>>>(px, pproj, ln1g, ln1b, px1, px116);

    // 6. FFN + LN2
    {
        Jobs<1> jb; jb.j[0] = { px116, w116, nullptr, ph16, {b1, nullptr, nullptr, 0, 1, 0} };
        tgemm<0,0,1><<<dim3(32,128,1), 128, TG_SMEM>>>(jb, DD, DFF, DFF, TROWS, DFF, DD);
    }
    {
        Jobs<1> jb; jb.j[0] = { ph16, w216, pf, nullptr, {b2, nullptr, nullptr, 0, 0, 0} };
        tgemm<0,0,1><<<dim3(8,128,1), 128, TG_SMEM>>>(jb, DFF, DD, DD, TROWS, DD, DFF);
    }
    ln_kernel<<<TROWS, 128>>>(px1, pf, ln2g, ln2b, nullptr, px216);

    // 7. output heads (merged l+r, guarded cols)
    {
        Jobs<2> jb;
        jb.j[0] = { px216,      pwl, outp,                 nullptr, {b_out_l, mask_l, pad, 0, 0, HAND_DIM} };
        jb.j[1] = { px216 + DD, pwr, outp + ROWS*HAND_DIM, nullptr, {b_out_r, mask_r, pad, 1, 0, HAND_DIM} };
        tgemm<2,1,2><<<dim3(2,64,2), 128, TG_SMEM>>>(jb, 2*DD, 128, HAND_DIM, ROWS, 128, DD);
    }
}

// round 17
// speedup vs baseline: 1.0552x; 1.0408x over previous
#include <cuda_runtime.h>
#include <cuda_fp16.h>
#include <math.h>

// ---------------------------------------------------------------------------
// Shapes
// ---------------------------------------------------------------------------
#define BB 32
#define LL 128
#define NN 512
#define JJ 21
#define HAND_DIM 99
#define DD 512
#define HH 8
#define DHH 64
#define DFF 2048
#define CAT 1249
#define CATP 1280
#define SS 256
#define ROWS 4096
#define TROWS 8192

#define F_X 0
#define F_J 99
#define F_MC 162
#define F_PCN 674
#define F_ATT 1186

// ---------------------------------------------------------------------------
// Scratch
// ---------------------------------------------------------------------------
__device__ float g_x   [TROWS * DD];
__device__ float g_q   [TROWS * DD];
__device__ float g_proj[TROWS * DD];
__device__ float g_x1  [TROWS * DD];
__device__ float g_f   [TROWS * DD];

__device__ __align__(16) __half g_feat16_l[ROWS * CATP];
__device__ __align__(16) __half g_feat16_r[ROWS * CATP];
__device__ __align__(16) __half g_x16  [TROWS * DD];
__device__ __align__(16) __half g_k16  [TROWS * DD];
__device__ __align__(16) __half g_v16  [TROWS * DD];
__device__ __align__(16) __half g_ao16 [TROWS * DD];
__device__ __align__(16) __half g_x116 [TROWS * DD];
__device__ __align__(16) __half g_h16  [TROWS * DFF];
__device__ __align__(16) __half g_x216 [TROWS * DD];

__device__ __align__(16) __half g_wfc_l16[CAT * DD];
__device__ __align__(16) __half g_wfc_r16[CAT * DD];
__device__ __align__(16) __half g_wq16 [DD * DD];
__device__ __align__(16) __half g_wk16 [DD * DD];
__device__ __align__(16) __half g_wv16 [DD * DD];
__device__ __align__(16) __half g_wo16 [DD * DD];
__device__ __align__(16) __half g_w116 [DD * DFF];
__device__ __align__(16) __half g_w216 [DFF * DD];
__device__ __align__(16) __half g_woutl16[DD * 128];
__device__ __align__(16) __half g_woutr16[DD * 128];

// ---------------------------------------------------------------------------
// Weight conversion
// ---------------------------------------------------------------------------
struct CvtJobs {
    const float* src[8];
    __half* dst[8];
    int n4[8];
};
__global__ void cvt_weights_kernel(CvtJobs cj)
{
    int gid = blockIdx.x * blockDim.x + threadIdx.x;
    int stride = gridDim.x * blockDim.x;
    #pragma unroll
    for (int j = 0; j < 8; j++) {
        const float4* s = (const float4*)cj.src[j];
        __half2* d = (__half2*)cj.dst[j];
        int n4 = cj.n4[j];
        for (int i = gid; i < n4; i += stride) {
            float4 v = s[i];
            d[2*i]   = __floats2half2_rn(v.x, v.y);
            d[2*i+1] = __floats2half2_rn(v.z, v.w);
        }
    }
}

__global__ void pad_wout_kernel(const float* __restrict__ Wl, const float* __restrict__ Wr,
                                __half* __restrict__ dl, __half* __restrict__ dr)
{
    int idx = blockIdx.x * 256 + threadIdx.x;
    int row = idx >> 7, col = idx & 127;
    float vl = (col < HAND_DIM) ? Wl[row*HAND_DIM + col] : 0.f;
    float vr = (col < HAND_DIM) ? Wr[row*HAND_DIM + col] : 0.f;
    dl[idx] = __float2half_rn(vl);
    dr[idx] = __float2half_rn(vr);
}

// ---------------------------------------------------------------------------
// Feature build -> fp16
// ---------------------------------------------------------------------------
__global__ void build_features_kernel(
    const float* __restrict__ x_l, const float* __restrict__ x_r,
    const float* __restrict__ j_l, const float* __restrict__ j_r,
    const float* __restrict__ m_contact, const float* __restrict__ pc,
    __half* __restrict__ feat_l, __half* __restrict__ feat_r)
{
    int m = blockIdx.x;
    int b = m >> 7;
    __shared__ float px[NN], py[NN], pz[NN];
    int tid = threadIdx.x;

    const float* pcb = pc + (size_t)m * NN * 3;
    for (int n = tid; n < NN; n += 256) {
        px[n] = pcb[n*3+0]; py[n] = pcb[n*3+1]; pz[n] = pcb[n*3+2];
    }
    __syncthreads();

    __half* fl = feat_l + (size_t)m * CATP;
    __half* fr = feat_r + (size_t)m * CATP;

    for (int i = tid; i < HAND_DIM; i += 256) {
        fl[F_X+i] = __float2half_rn(x_l[(size_t)m*HAND_DIM + i]);
        fr[F_X+i] = __float2half_rn(x_r[(size_t)m*HAND_DIM + i]);
    }
    for (int i = tid; i < JJ*3; i += 256) {
        fl[F_J+i] = __float2half_rn(j_l[(size_t)m*JJ*3 + i]);
        fr[F_J+i] = __float2half_rn(j_r[(size_t)m*JJ*3 + i]);
    }
    for (int n = tid; n < NN; n += 256) {
        __half mc = __float2half_rn(m_contact[b*NN + n]);
        fl[F_MC+n] = mc; fr[F_MC+n] = mc;
        __half nm = __float2half_rn(sqrtf(px[n]*px[n] + py[n]*py[n] + pz[n]*pz[n]));
        fl[F_PCN+n] = nm; fr[F_PCN+n] = nm;
    }
    __half z = __float2half_rn(0.f);
    for (int i = CAT + tid; i < CATP; i += 256) { fl[i] = z; fr[i] = z; }

    int w = tid >> 5, lane = tid & 31;
    for (int task = w; task < 2*JJ; task += 8) {
        int hand = task / JJ, joint = task % JJ;
        const float* jb = (hand == 0 ? j_l : j_r) + ((size_t)m*JJ + joint)*3;
        float jx = jb[0], jy = jb[1], jz = jb[2];
        float best = 3.402823466e+38f; int bi = 0;
        for (int n = lane; n < NN; n += 32) {
            float dx = jx - px[n], dy = jy - py[n], dz = jz - pz[n];
            float d2 = dx*dx + dy*dy + dz*dz;
            if (d2 < best) { best = d2; bi = n; }
        }
        for (int off = 16; off; off >>= 1) {
            float ob = __shfl_xor_sync(0xffffffffu, best, off);
            int   oi = __shfl_xor_sync(0xffffffffu, bi, off);
            if (ob < best || (ob == best && oi < bi)) { best = ob; bi = oi; }
        }
        if (lane == 0) {
            float dx = jx - px[bi], dy = jy - py[bi], dz = jz - pz[bi];
            __half* f = (hand == 0 ? fl : fr);
            f[F_ATT + joint*3 + 0] = __float2half_rn(expf(-50.f * dx * dx));
            f[F_ATT + joint*3 + 1] = __float2half_rn(expf(-50.f * dy * dy));
            f[F_ATT + joint*3 + 2] = __float2half_rn(expf(-50.f * dz * dz));
        }
    }
}

// ---------------------------------------------------------------------------
// Epilogues
// ---------------------------------------------------------------------------
struct EpiParams {
    const float* bias;
    const float* mask;
    const unsigned char* pad;
    int hand;
    int relu;
    int nreal;
};

#define LN10000 9.2103403719761827f

template<int EPI>
__device__ __forceinline__ float apply_epi(float v, int row, int col, const EpiParams& ep)
{
    if (EPI == 0) {
        if (ep.bias) v += ep.bias[col];
        if (ep.relu) v = fmaxf(v, 0.f);
    } else if (EPI == 1) {
        int l = row & 127;
        int ii = col >> 1;
        float freq = expf(-LN10000 * (float)ii * (1.f/256.f));
        float angF = (float)l * freq;
        float angA = (float)ep.hand * freq;
        float pe = (col & 1) ? (cosf(angF) + cosf(angA))
                             : (sinf(angF) + sinf(angA));
        float mv = ep.mask[row] * (ep.pad[2*row + ep.hand] ? 0.f : 1.f);
        v = (v + ep.bias[col] + pe) * mv;
    } else { // EPI == 2
        float mv = ep.mask[row] * (ep.pad[2*row + ep.hand] ? 0.f : 1.f);
        v = (v + ep.bias[col]) * mv;
    }
    return v;
}

// ---------------------------------------------------------------------------
// Multi-job single-pass fp16 GEMM, 2-stage cp.async.
// 128 threads, CTA tile 64x128, BK=32, 4 warps (2x2; warp tile 32x64),
// 4 CTAs/SM. N must be a multiple of 128.
// ---------------------------------------------------------------------------
struct Job { const __half* A; const __half* B; float* C; __half* C16; EpiParams ep; };
template<int NJ> struct Jobs { Job j[NJ]; };

#define PA 80                           // A pitch bytes (32 halves + pad)
#define PB 272                          // B pitch bytes (128 halves + 8 pad; 17 granules)
#define A_BYTES (64*PA)                 // 5120
#define B_BYTES (32*PB)                 // 8704
#define OFF_AH 0
#define OFF_BH (A_BYTES)
#define BUF_BYTES (A_BYTES + B_BYTES)   // 13824
#define TG_SMEM (2*BUF_BYTES)           // 27648

__device__ __forceinline__ unsigned smem_u32(const void* p) {
    return (unsigned)__cvta_generic_to_shared(p);
}
__device__ __forceinline__ void ldsm4(unsigned* r, unsigned addr) {
    asm volatile("ldmatrix.sync.aligned.m8n8.x4.shared.b16 {%0,%1,%2,%3}, [%4];"
        : "=r"(r[0]), "=r"(r[1]), "=r"(r[2]), "=r"(r[3]) : "r"(addr));
}
__device__ __forceinline__ void ldsm4t(unsigned* r, unsigned addr) {
    asm volatile("ldmatrix.sync.aligned.m8n8.x4.trans.shared.b16 {%0,%1,%2,%3}, [%4];"
        : "=r"(r[0]), "=r"(r[1]), "=r"(r[2]), "=r"(r[3]) : "r"(addr));
}
__device__ __forceinline__ void mma16816(float* c, const unsigned* a, unsigned b0, unsigned b1) {
    asm volatile(
        "mma.sync.aligned.m16n8k16.row.col.f32.f16.f16.f32 "
        "{%0,%1,%2,%3}, {%4,%5,%6,%7}, {%8,%9}, {%0,%1,%2,%3};"
        : "+f"(c[0]), "+f"(c[1]), "+f"(c[2]), "+f"(c[3])
        : "r"(a[0]), "r"(a[1]), "r"(a[2]), "r"(a[3]), "r"(b0), "r"(b1));
}
__device__ __forceinline__ void cp16(unsigned dst, const void* src, bool full) {
    int sz = full ? 16 : 0;
    asm volatile("cp.async.cg.shared.global [%0], [%1], 16, %2;"
                 :: "r"(dst), "l"(src), "r"(sz) : "memory");
}
__device__ __forceinline__ void cp_commit() {
    asm volatile("cp.async.commit_group;" ::: "memory");
}
template<int N> __device__ __forceinline__ void cp_wait() {
    asm volatile("cp.async.wait_group %0;" :: "n"(N) : "memory");
}

template<int EPI, int GUARD, int NJ>
__global__ __launch_bounds__(128, 4)
void tgemm(Jobs<NJ> jobs, int lda, int ldb, int ldc, int M, int N, int Kreal)
{
    const Job& jb = jobs.j[blockIdx.z];
    const __half* __restrict__ A = jb.A;
    const __half* __restrict__ B = jb.B;
    float* __restrict__ C = jb.C;
    __half* __restrict__ C16 = jb.C16;
    EpiParams ep = jb.ep;

    extern __shared__ unsigned char smraw[];
    unsigned sbase = smem_u32(smraw);
    int tid = threadIdx.x, lane = tid & 31, wid = tid >> 5;
    int warp_m = wid & 1, warp_n = wid >> 1;
    int m0 = blockIdx.y * 64, n0 = blockIdx.x * 128;
    int g = lane >> 2, t = lane & 3;

    float acc[2][8][4];
    #pragma unroll
    for (int i = 0; i < 2; i++)
        #pragma unroll
        for (int j = 0; j < 8; j++)
            #pragma unroll
            for (int e = 0; e < 4; e++) acc[i][j][e] = 0.f;

    int aRow = lane & 15;
    int aKof = ((lane >> 4) & 1) * 8;
    int bRow = lane & 15;
    int bNof = ((lane >> 4) & 1) * 8;

    int nk = (Kreal + 31) >> 5;

    auto prefetch = [&](int kt) {
        int k0 = kt * 32;
        unsigned bufb = sbase + (kt & 1) * BUF_BYTES;
        // A: 64 rows x 64B = 256 chunks (2/thread)
        #pragma unroll
        for (int i = 0; i < 2; i++) {
            int c = tid + 128*i;
            int r = c >> 2, col8 = (c & 3) * 8;
            cp16(bufb + OFF_AH + r*PA + col8*2,
                 A + (size_t)(m0 + r)*lda + k0 + col8, true);
        }
        // B: 32 rows x 256B = 512 chunks (4/thread)
        #pragma unroll
        for (int i = 0; i < 4; i++) {
            int c = tid + 128*i;
            int r = c >> 4, col8 = (c & 15) * 8;
            int k = k0 + r;
            int ksafe = (k < Kreal) ? k : (Kreal - 1);
            cp16(bufb + OFF_BH + r*PB + col8*2,
                 B + (size_t)ksafe*ldb + n0 + col8, k < Kreal);
        }
        cp_commit();
    };

    prefetch(0);

    for (int kt = 0; kt < nk; kt++) {
        if (kt + 1 < nk) { prefetch(kt + 1); cp_wait<1>(); }
        else             { cp_wait<0>(); }
        __syncthreads();

        unsigned base = sbase + (kt & 1) * BUF_BYTES;
        #pragma unroll
        for (int ks = 0; ks < 2; ks++) {
            unsigned aAddrBase = base + (ks*16 + aKof) * 2;
            unsigned bAddrBase = base + (ks*16 + bRow) * PB;

            unsigned ah[2][4], bh[4][4];
            #pragma unroll
            for (int mt = 0; mt < 2; mt++)
                ldsm4(ah[mt], aAddrBase + OFF_AH + (warp_m*32 + mt*16 + aRow)*PA);
            #pragma unroll
            for (int np = 0; np < 4; np++)
                ldsm4t(bh[np], bAddrBase + OFF_BH + (warp_n*64 + np*16 + bNof)*2);

            #pragma unroll
            for (int mt = 0; mt < 2; mt++)
                #pragma unroll
                for (int nt = 0; nt < 8; nt++)
                    mma16816(acc[mt][nt], ah[mt], bh[nt>>1][(nt&1)*2], bh[nt>>1][(nt&1)*2+1]);
        }
        __syncthreads();
    }

    #pragma unroll
    for (int mt = 0; mt < 2; mt++) {
        int row0 = m0 + warp_m*32 + mt*16 + g;
        #pragma unroll
        for (int nt = 0; nt < 8; nt++) {
            int col = n0 + warp_n*64 + nt*8 + t*2;
            float* c = acc[mt][nt];
            float v0 = apply_epi<EPI>(c[0], row0,     col,     ep);
            float v1 = apply_epi<EPI>(c[1], row0,     col + 1, ep);
            float v2 = apply_epi<EPI>(c[2], row0 + 8, col,     ep);
            float v3 = apply_epi<EPI>(c[3], row0 + 8, col + 1, ep);
            if (GUARD) {
                if (C) {
                    if (col < ep.nreal)     C[(size_t)row0*ldc + col]         = v0;
                    if (col + 1 < ep.nreal) C[(size_t)row0*ldc + col + 1]     = v1;
                    if (col < ep.nreal)     C[(size_t)(row0+8)*ldc + col]     = v2;
                    if (col + 1 < ep.nreal) C[(size_t)(row0+8)*ldc + col + 1] = v3;
                }
            } else {
                if (C) {
                    *(float2*)(C + (size_t)row0*ldc + col)       = make_float2(v0, v1);
                    *(float2*)(C + (size_t)(row0 + 8)*ldc + col) = make_float2(v2, v3);
                }
                if (C16) {
                    __half2 h01 = __floats2half2_rn(v0, v1);
                    __half2 h23 = __floats2half2_rn(v2, v3);
                    *(__half2*)(C16 + (size_t)row0*ldc + col)       = h01;
                    *(__half2*)(C16 + (size_t)(row0 + 8)*ldc + col) = h23;
                }
            }
        }
    }
}

// ---------------------------------------------------------------------------
// Fused attention, q-split x2 (R14 proven)
// ---------------------------------------------------------------------------
#define KP 72
#define VTP 258
#define ATT_K_OFF 0
#define ATT_VT_OFF 36864
#define ATT_PS_OFF 69888
#define ATT_QS_OFF 86272
#define ATT_BS_OFF 90368
#define ATT_SMEM 91392

__global__ __launch_bounds__(256, 2)
void attention_kernel(const float* __restrict__ qb,
                      const __half* __restrict__ kb,
                      const __half* __restrict__ vb,
                      const unsigned char* __restrict__ pad,
                      __half* __restrict__ ob)
{
    int blk = blockIdx.x;
    int bh = blk >> 1;
    int qhalf = blk & 1;
    int b = bh >> 3, h = bh & 7;
    extern __shared__ unsigned char smb[];
    __half* Ks = (__half*)(smb + ATT_K_OFF);
    __half* Vt = (__half*)(smb + ATT_VT_OFF);
    float* Ps  = (float*)(smb + ATT_PS_OFF);
    float* Qs  = (float*)(smb + ATT_QS_OFF);
    float* Bsb = (float*)(smb + ATT_BS_OFF);

    int tid = threadIdx.x, lane = tid & 31, w = tid >> 5;
    const __half* kbase = kb + (size_t)(b*SS)*DD + h*DHH;
    const __half* vbase = vb + (size_t)(b*SS)*DD + h*DHH;

    for (int idx = tid; idx < 256*64; idx += 256) {
        int r = idx >> 6, c = idx & 63;
        Ks[r*KP + c]  = kbase[(size_t)r*DD + c];
        Vt[c*VTP + r] = vbase[(size_t)r*DD + c];
    }
    if (tid < 256) Bsb[tid] = pad[b*SS + tid] ? -1e9f : 0.f;
    __syncthreads();

    float* Pw0 = Ps + (2*w + 0)*256;
    float* Pw1 = Ps + (2*w + 1)*256;
    float* Qw = Qs + w*128;

    int q0base = qhalf * 128;
    for (int qi = q0base + 2*w; qi < q0base + 128; qi += 16) {
        const float* q0 = qb + (size_t)(b*SS + qi)*DD + h*DHH;
        Qw[lane]           = q0[lane];
        Qw[lane + 32]      = q0[lane + 32];
        Qw[64 + lane]      = q0[DD + lane];
        Qw[64 + lane + 32] = q0[DD + lane + 32];
        __syncwarp();

        const float4* q4a = (const float4*)Qw;
        const float4* q4b = (const float4*)(Qw + 64);

        float s0[8], s1[8];
        float mx0 = -3.402823466e+38f, mx1 = -3.402823466e+38f;
        #pragma unroll
        for (int k8 = 0; k8 < 8; k8++) {
            int j = lane + 32*k8;
            const uint4* kr4 = (const uint4*)(Ks + j*KP);
            float a0 = 0.f, a1 = 0.f;
            #pragma unroll
            for (int d8 = 0; d8 < 8; d8++) {
                uint4 kv = kr4[d8];
                float2 f0 = __half22float2(*(__half2*)&kv.x);
                float2 f1 = __half22float2(*(__half2*)&kv.y);
                float2 f2 = __half22float2(*(__half2*)&kv.z);
                float2 f3 = __half22float2(*(__half2*)&kv.w);
                float4 qa0 = q4a[d8*2],   qa1 = q4a[d8*2+1];
                float4 qb0 = q4b[d8*2],   qb1 = q4b[d8*2+1];
                a0 += qa0.x*f0.x + qa0.y*f0.y + qa0.z*f1.x + qa0.w*f1.y
                    + qa1.x*f2.x + qa1.y*f2.y + qa1.z*f3.x + qa1.w*f3.y;
                a1 += qb0.x*f0.x + qb0.y*f0.y + qb0.z*f1.x + qb0.w*f1.y
                    + qb1.x*f2.x + qb1.y*f2.y + qb1.z*f3.x + qb1.w*f3.y;
            }
            float bias = Bsb[j];
            a0 = a0 * 0.125f + bias;
            a1 = a1 * 0.125f + bias;
            s0[k8] = a0; s1[k8] = a1;
            mx0 = fmaxf(mx0, a0); mx1 = fmaxf(mx1, a1);
        }
        for (int off = 16; off; off >>= 1) {
            mx0 = fmaxf(mx0, __shfl_xor_sync(0xffffffffu, mx0, off));
            mx1 = fmaxf(mx1, __shfl_xor_sync(0xffffffffu, mx1, off));
        }
        float sm0 = 0.f, sm1 = 0.f;
        #pragma unroll
        for (int k8 = 0; k8 < 8; k8++) {
            s0[k8] = __expf(s0[k8] - mx0); sm0 += s0[k8];
            s1[k8] = __expf(s1[k8] - mx1); sm1 += s1[k8];
        }
        for (int off = 16; off; off >>= 1) {
            sm0 += __shfl_xor_sync(0xffffffffu, sm0, off);
            sm1 += __shfl_xor_sync(0xffffffffu, sm1, off);
        }
        float i0 = 1.f / sm0, i1 = 1.f / sm1;
        #pragma unroll
        for (int k8 = 0; k8 < 8; k8++) {
            Pw0[lane + 32*k8] = s0[k8]*i0;
            Pw1[lane + 32*k8] = s1[k8]*i1;
        }
        __syncwarp();

        const __half2* vtA = (const __half2*)(Vt + (size_t)lane*VTP);
        const __half2* vtB = (const __half2*)(Vt + (size_t)(lane+32)*VTP);
        const float2* P02 = (const float2*)Pw0;
        const float2* P12 = (const float2*)Pw1;
        float o00 = 0.f, o01 = 0.f, o10 = 0.f, o11 = 0.f;
        for (int j2 = 0; j2 < 128; j2++) {
            float2 p0 = P02[j2];
            float2 p1 = P12[j2];
            float2 vA = __half22float2(vtA[j2]);
            float2 vB = __half22float2(vtB[j2]);
            o00 += p0.x*vA.x + p0.y*vA.y;
            o01 += p0.x*vB.x + p0.y*vB.y;
            o10 += p1.x*vA.x + p1.y*vA.y;
            o11 += p1.x*vB.x + p1.y*vB.y;
        }
        __half* orow = ob + (size_t)(b*SS + qi)*DD + h*DHH;
        orow[lane]           = __float2half_rn(o00);
        orow[lane + 32]      = __float2half_rn(o01);
        orow[DD + lane]      = __float2half_rn(o10);
        orow[DD + lane + 32] = __float2half_rn(o11);
        __syncwarp();
    }
}

// ---------------------------------------------------------------------------
// Residual add + LayerNorm
// ---------------------------------------------------------------------------
__global__ void ln_kernel(const float* __restrict__ x, const float* __restrict__ add,
                          const float* __restrict__ g, const float* __restrict__ bv,
                          float* __restrict__ out, __half* __restrict__ out16)
{
    int t = blockIdx.x;
    int tid = threadIdx.x;
    const float* xr = x   + (size_t)t*DD;
    const float* ar = add + (size_t)t*DD;
    float v[4];
    float s = 0.f, ss = 0.f;
    #pragma unroll
    for (int i = 0; i < 4; i++) {
        float u = xr[tid + 128*i] + ar[tid + 128*i];
        v[i] = u; s += u; ss += u*u;
    }
    for (int off = 16; off; off >>= 1) {
        s  += __shfl_xor_sync(0xffffffffu, s,  off);
        ss += __shfl_xor_sync(0xffffffffu, ss, off);
    }
    __shared__ float rs[4], rss[4];
    int w = tid >> 5, lane = tid & 31;
    if (lane == 0) { rs[w] = s; rss[w] = ss; }
    __syncthreads();
    s  = rs[0]+rs[1]+rs[2]+rs[3];
    ss = rss[0]+rss[1]+rss[2]+rss[3];
    float mean = s * (1.f/512.f);
    float var  = ss * (1.f/512.f) - mean*mean;
    float rstd = rsqrtf(var + 1e-5f);
    #pragma unroll
    for (int i = 0; i < 4; i++) {
        int c = tid + 128*i;
        float o = (v[i]-mean)*rstd*g[c] + bv[c];
        if (out)   out[(size_t)t*DD + c] = o;
        if (out16) out16[(size_t)t*DD + c] = __float2half_rn(o);
    }
}

// ---------------------------------------------------------------------------
// Launch
// ---------------------------------------------------------------------------
extern "C" void kernel_launch(void* const* d_in, const int* in_sizes, int n_in,
                              void* d_out, int out_size)
{
    const float* x_l  = (const float*)d_in[0];
    const float* x_r  = (const float*)d_in[1];
    const float* j_l  = (const float*)d_in[2];
    const float* j_r  = (const float*)d_in[3];
    const float* mcon = (const float*)d_in[4];
    const float* pc   = (const float*)d_in[5];
    const float* mask_l = (const float*)d_in[6];
    const float* mask_r = (const float*)d_in[7];
    const unsigned char* pad = (const unsigned char*)d_in[8];
    const float* W_fc_l = (const float*)d_in[9];
    const float* b_fc_l = (const float*)d_in[10];
    const float* W_fc_r = (const float*)d_in[11];
    const float* b_fc_r = (const float*)d_in[12];
    const float* Wq = (const float*)d_in[13];
    const float* Wk = (const float*)d_in[14];
    const float* Wv = (const float*)d_in[15];
    const float* Wo = (const float*)d_in[16];
    const float* W1 = (const float*)d_in[17];
    const float* b1 = (const float*)d_in[18];
    const float* W2 = (const float*)d_in[19];
    const float* b2 = (const float*)d_in[20];
    const float* ln1g = (const float*)d_in[21];
    const float* ln1b = (const float*)d_in[22];
    const float* ln2g = (const float*)d_in[23];
    const float* ln2b = (const float*)d_in[24];
    const float* W_out_l = (const float*)d_in[25];
    const float* b_out_l = (const float*)d_in[26];
    const float* W_out_r = (const float*)d_in[27];
    const float* b_out_r = (const float*)d_in[28];
    float* outp = (float*)d_out;

    float *px, *pq, *pproj, *px1, *pf;
    __half *pfl16, *pfr16, *px16, *pk16, *pv16, *pao16, *px116, *ph16, *px216;
    __half *wfcl, *wfcr, *wq16, *wk16, *wv16, *wo16, *w116, *w216, *pwl, *pwr;
    cudaGetSymbolAddress((void**)&px,    g_x);
    cudaGetSymbolAddress((void**)&pq,    g_q);
    cudaGetSymbolAddress((void**)&pproj, g_proj);
    cudaGetSymbolAddress((void**)&px1,   g_x1);
    cudaGetSymbolAddress((void**)&pf,    g_f);
    cudaGetSymbolAddress((void**)&pfl16, g_feat16_l);
    cudaGetSymbolAddress((void**)&pfr16, g_feat16_r);
    cudaGetSymbolAddress((void**)&px16,  g_x16);
    cudaGetSymbolAddress((void**)&pk16,  g_k16);
    cudaGetSymbolAddress((void**)&pv16,  g_v16);
    cudaGetSymbolAddress((void**)&pao16, g_ao16);
    cudaGetSymbolAddress((void**)&px116, g_x116);
    cudaGetSymbolAddress((void**)&ph16,  g_h16);
    cudaGetSymbolAddress((void**)&px216, g_x216);
    cudaGetSymbolAddress((void**)&wfcl,  g_wfc_l16);
    cudaGetSymbolAddress((void**)&wfcr,  g_wfc_r16);
    cudaGetSymbolAddress((void**)&wq16,  g_wq16);
    cudaGetSymbolAddress((void**)&wk16,  g_wk16);
    cudaGetSymbolAddress((void**)&wv16,  g_wv16);
    cudaGetSymbolAddress((void**)&wo16,  g_wo16);
    cudaGetSymbolAddress((void**)&w116,  g_w116);
    cudaGetSymbolAddress((void**)&w216,  g_w216);
    cudaGetSymbolAddress((void**)&pwl,   g_woutl16);
    cudaGetSymbolAddress((void**)&pwr,   g_woutr16);

    cudaFuncSetAttribute((const void*)tgemm<0,0,1>, cudaFuncAttributeMaxDynamicSharedMemorySize, TG_SMEM);
    cudaFuncSetAttribute((const void*)tgemm<0,0,3>, cudaFuncAttributeMaxDynamicSharedMemorySize, TG_SMEM);
    cudaFuncSetAttribute((const void*)tgemm<1,0,2>, cudaFuncAttributeMaxDynamicSharedMemorySize, TG_SMEM);
    cudaFuncSetAttribute((const void*)tgemm<2,1,2>, cudaFuncAttributeMaxDynamicSharedMemorySize, TG_SMEM);
    cudaFuncSetAttribute(attention_kernel,
                         cudaFuncAttributeMaxDynamicSharedMemorySize, ATT_SMEM);

    EpiParams none = {nullptr, nullptr, nullptr, 0, 0, 0};

    // 0. weight conversion + head-weight padding
    {
        CvtJobs cj;
        cj.src[0] = W_fc_l; cj.dst[0] = wfcl; cj.n4[0] = (CAT*DD)/4;
        cj.src[1] = W_fc_r; cj.dst[1] = wfcr; cj.n4[1] = (CAT*DD)/4;
        cj.src[2] = Wq;     cj.dst[2] = wq16; cj.n4[2] = (DD*DD)/4;
        cj.src[3] = Wk;     cj.dst[3] = wk16; cj.n4[3] = (DD*DD)/4;
        cj.src[4] = Wv;     cj.dst[4] = wv16; cj.n4[4] = (DD*DD)/4;
        cj.src[5] = Wo;     cj.dst[5] = wo16; cj.n4[5] = (DD*DD)/4;
        cj.src[6] = W1;     cj.dst[6] = w116; cj.n4[6] = (DD*DFF)/4;
        cj.src[7] = W2;     cj.dst[7] = w216; cj.n4[7] = (DFF*DD)/4;
        cvt_weights_kernel<<<1024, 256>>>(cj);
    }
    pad_wout_kernel<<<256, 256>>>(W_out_l, W_out_r, pwl, pwr);

    // 1. features (fp16)
    build_features_kernel<<<ROWS, 256>>>(x_l, x_r, j_l, j_r, mcon, pc, pfl16, pfr16);

    // 2. fc projections (merged l+r): 4x64x2 = 512 CTAs, one wave
    {
        Jobs<2> jb;
        jb.j[0] = { pfl16, wfcl, px,      px16,      {b_fc_l, mask_l, pad, 0, 0, 0} };
        jb.j[1] = { pfr16, wfcr, px + DD, px16 + DD, {b_fc_r, mask_r, pad, 1, 0, 0} };
        tgemm<1,0,2><<<dim3(4,64,2), 128, TG_SMEM>>>(jb, CATP, DD, 2*DD, ROWS, DD, CAT);
    }

    // 3. QKV (merged): 4x128x3 = 1536 CTAs
    {
        Jobs<3> jb;
        jb.j[0] = { px16, wq16, pq,      nullptr, none };
        jb.j[1] = { px16, wk16, nullptr, pk16,    none };
        jb.j[2] = { px16, wv16, nullptr, pv16,    none };
        tgemm<0,0,3><<<dim3(4,128,3), 128, TG_SMEM>>>(jb, DD, DD, DD, TROWS, DD, DD);
    }

    // 4. attention (q-split x2)
    attention_kernel<<<BB*HH*2, 256, ATT_SMEM>>>(pq, pk16, pv16, pad, pao16);

    // 5. Wo + LN1: 512 CTAs
    {
        Jobs<1> jb; jb.j[0] = { pao16, wo16, pproj, nullptr, none };
        tgemm<0,0,1><<<dim3(4,128,1), 128, TG_SMEM>>>(jb, DD, DD, DD, TROWS, DD, DD);
    }
    ln_kernel<<<TROWS, 128>>>(px, pproj, ln1g, ln1b, px1, px116);

    // 6. FFN + LN2: 2048 / 512 CTAs
    {
        Jobs<1> jb; jb.j[0] = { px116, w116, nullptr, ph16, {b1, nullptr, nullptr, 0, 1, 0} };
        tgemm<0,0,1><<<dim3(16,128,1), 128, TG_SMEM>>>(jb, DD, DFF, DFF, TROWS, DFF, DD);
    }
    {
        Jobs<1> jb; jb.j[0] = { ph16, w216, pf, nullptr, {b2, nullptr, nullptr, 0, 0, 0} };
        tgemm<0,0,1><<<dim3(4,128,1), 128, TG_SMEM>>>(jb, DFF, DD, DD, TROWS, DD, DFF);
    }
    ln_kernel<<<TROWS, 128>>>(px1, pf, ln2g, ln2b, nullptr, px216);

    // 7. output heads (merged l+r, guarded cols): 1x64x2 = 128 CTAs
    {
        Jobs<2> jb;
        jb.j[0] = { px216,      pwl, outp,                 nullptr, {b_out_l, mask_l, pad, 0, 0, HAND_DIM} };
        jb.j[1] = { px216 + DD, pwr, outp + ROWS*HAND_DIM, nullptr, {b_out_r, mask_r, pad, 1, 0, HAND_DIM} };
        tgemm<2,1,2><<<dim3(1,64,2), 128, TG_SMEM>>>(jb, 2*DD, 128, HAND_DIM, ROWS, 128, DD);
    }
}